// round 8
// baseline (speedup 1.0000x reference)
#include <cuda_runtime.h>
#include <cstddef>

// ---- problem constants ----
#define HH 384
#define WW 384
#define NPIX (HH*WW)          // 147456
#define BB 4
#define MM 192
#define NT 512
#define TILE_W 64
#define TILE_H 32
#define TILES_X (WW/TILE_W)            // 6
#define TILES_Y (HH/TILE_H)            // 12
#define NCHUNK (TILES_X*TILES_Y)       // 72
#define NBLK1 (BB*NCHUNK)              // 288
#define NBLK2 ((BB*MM)/16)             // 48 (16 warps/block, 1 warp per (b,j))
#define TOTBLK (NBLK1+NBLK2)           // 336
#define NWARP (NT/32)                  // 16
#define EPSF 1e-6f
#define MAX_DISTF 543.0580079975699f   // sqrt(384^2+384^2)
#define EPS_OVER_MAX 1.8414263e-9f     // 1e-6 / MAX_DIST
#define C2MIN 0.999999f
#define BIGF 3.4e38f

// ---- scratch (static device globals; g_sem reset by finalizer) ----
__device__ float    g_t1part[NBLK1];
__device__ float    g_ppart [NBLK1];
__device__ float    g_jval  [BB*MM];
__device__ unsigned g_sem;

// ---- packed f32x2 helpers ----
__device__ __forceinline__ unsigned long long pk2(float a, float b) {
    unsigned long long r;
    asm("mov.b64 %0, {%1, %2};" : "=l"(r) : "f"(a), "f"(b));
    return r;
}
__device__ __forceinline__ void upk2(float& a, float& b, unsigned long long v) {
    asm("mov.b64 {%0, %1}, %2;" : "=f"(a), "=f"(b) : "l"(v));
}
__device__ __forceinline__ unsigned long long addx2(unsigned long long a, unsigned long long b) {
    unsigned long long r;
    asm("add.rn.f32x2 %0, %1, %2;" : "=l"(r) : "l"(a), "l"(b));
    return r;
}
__device__ __forceinline__ unsigned long long fmax2(unsigned long long a, unsigned long long b,
                                                    unsigned long long c) {
    unsigned long long r;
    asm("fma.rn.f32x2 %0, %1, %2, %3;" : "=l"(r) : "l"(a), "l"(b), "l"(c));
    return r;
}

__global__ __launch_bounds__(NT, 2)
void whd_all(const float* __restrict__ pm,
             const float* __restrict__ gt,
             const float* __restrict__ osz,
             float* __restrict__ out)
{
    __shared__ ulonglong2 s_cand[MM];   // {(-gx,-gx), (-gy,-gy)} packed -> LDS.128
    __shared__ float s_red[NWARP*2];
    __shared__ float s_t1[BB];
    __shared__ int   s_n;
    __shared__ bool  s_last;

    const int tid  = threadIdx.x;
    const int lane = tid & 31;
    const int wid  = tid >> 5;
    const int bid  = blockIdx.x;

    if (tid == 0) s_n = 0;

    if (bid < NBLK2) {
        // ==================== term2 role: one warp per (b,j) ====================
        // Exact windowed search for min over all pixels of d2*c^2.
        // Lane <-> column (coalesced row loads, no integer division, dx^2 hoisted);
        // row loop unrolled for MLP. Certified exact via edge-gap bound.
        const int wg = bid * NWARP + wid;          // 0..767
        const int b  = wg / MM;
        const int j  = wg - b * MM;

        const float fy = osz[2*b+0] * (1.0f/(float)HH);
        const float fx = osz[2*b+1] * (1.0f/(float)WW);
        const float grow = gt[((size_t)b*MM + j)*2 + 0];
        const float gcol = gt[((size_t)b*MM + j)*2 + 1];
        const float* pmb = pm + (size_t)b * NPIX;

        const int cx = (int)gcol;
        const int cy = (int)grow;

        float U;
        int r = 15;                                 // 31x31 start: nearly always certifies
        for (;;) {
            int x0 = cx - r, x1 = cx + r, y0 = cy - r, y1 = cy + r;
            const bool clx0 = (x0 <= 0), clx1 = (x1 >= WW-1);
            const bool cly0 = (y0 <= 0), cly1 = (y1 >= HH-1);
            x0 = max(x0, 0); y0 = max(y0, 0);
            x1 = min(x1, WW-1); y1 = min(y1, HH-1);

            float kmin = BIGF;
            for (int xs = x0; xs <= x1; xs += 32) {  // column strips of 32 lanes
                int px = xs + lane;
                if (px <= x1) {
                    float dxv = ((float)px - gcol) * fx;
                    float dx2 = dxv * dxv;
                    const float* rowp = pmb + (size_t)y0 * WW + px;
                    float dyv = ((float)y0 - grow) * fy;
#pragma unroll 4
                    for (int y = y0; y <= y1; ++y) {
                        float p  = *rowp;            // coalesced across lanes
                        rowp += WW;
                        float d2 = fmaf(dyv, dyv, dx2);
                        dyv += fy;
                        float pp = p*p;
                        float c  = __fdividef(1.0f, pp*pp + EPS_OVER_MAX);
                        kmin = fminf(kmin, d2 * (c*c));
                    }
                }
            }
            unsigned u = __reduce_min_sync(0xffffffffu, __float_as_uint(kmin));
            U = __uint_as_float(u);

            if (clx0 && clx1 && cly0 && cly1) break;   // full image: exact

            const float GBIG = 1.0e18f;
            float gxl = clx0 ? GBIG : (gcol - (float)x0 + 1.0f) * fx;
            float gxh = clx1 ? GBIG : ((float)x1 + 1.0f - gcol) * fx;
            float gyl = cly0 ? GBIG : (grow - (float)y0 + 1.0f) * fy;
            float gyh = cly1 ? GBIG : ((float)y1 + 1.0f - grow) * fy;
            float G = fminf(fminf(gxl, gxh), fminf(gyl, gyh));
            if (U <= G*G*C2MIN) break;                 // exactness certified
            r <<= 1;                                   // rare
        }
        if (lane == 0)
            g_jval[wg] = fminf(sqrtf(U), MAX_DISTF);
    } else {
        // ==================== term1 role: one 64x32 pixel tile ====================
        const int tb    = bid - NBLK2;             // 0..287
        const int b     = tb / NCHUNK;
        const int chunk = tb - b * NCHUNK;
        const int tile_x = chunk % TILES_X;
        const int tile_y = chunk / TILES_X;

        const float fy = osz[2*b+0] * (1.0f/(float)HH);
        const float fx = osz[2*b+1] * (1.0f/(float)WW);
        const float* pmb = pm + (size_t)b * NPIX;

        const int col0 = tile_x * TILE_W;
        const int row0 = tile_y * TILE_H;
        const int colg = col0 + (tid & 63);
        const int rowb = row0 + (tid >> 6);        // rows rowb, rowb+8, +16, +24

        // issue pixel loads early (overlap with phase-0 cull)
        float p0 = pmb[(rowb +  0)*WW + colg];
        float p1 = pmb[(rowb +  8)*WW + colg];
        float p2 = pmb[(rowb + 16)*WW + colg];
        float p3 = pmb[(rowb + 24)*WW + colg];

        const float xn  = (float)colg * fx;        // shared across this thread's 4 px
        const unsigned long long ny01 = pk2((float)(rowb +  0) * fy, (float)(rowb +  8) * fy);
        const unsigned long long ny23 = pk2((float)(rowb + 16) * fy, (float)(rowb + 24) * fy);

        // ---- phase 0: exact candidate culling (triangle inequality) ----
        const float cxn = ((float)col0 + 31.5f) * fx;
        const float cyn = ((float)row0 + 15.5f) * fy;
        const float hx = 31.5f * fx, hy = 15.5f * fy;
        const float Dh = sqrtf(hx*hx + hy*hy);     // tile half-diagonal (normalized)

        float dc = BIGF, gxn = 0.f, gyn = 0.f;
        if (tid < MM) {
            gyn = gt[((size_t)b*MM + tid)*2 + 0] * fy;
            gxn = gt[((size_t)b*MM + tid)*2 + 1] * fx;
            float ax = gxn - cxn, ay = gyn - cyn;
            dc = sqrtf(fmaf(ax, ax, ay*ay));
        }
        unsigned wm = __reduce_min_sync(0xffffffffu, __float_as_uint(dc));
        if (lane == 0) s_red[wid] = __uint_as_float(wm);
        __syncthreads();
        float Uc = fminf(fminf(fminf(s_red[0], s_red[1]), fminf(s_red[2], s_red[3])),
                         fminf(s_red[4], s_red[5]));
        // point j can be some tile pixel's argmin only if dc <= Uc + 2*Dh (+ slack)
        float thr = Uc + 2.0f*Dh + 1e-2f;
        if (tid < MM && dc <= thr) {
            int slot = atomicAdd(&s_n, 1);
            ulonglong2 v;
            v.x = pk2(-gxn, -gxn);
            v.y = pk2(-gyn, -gyn);
            s_cand[slot] = v;
        }
        __syncthreads();
        const int ncand = s_n;

        // ---- hot loop over candidates only ----
        float d0 = BIGF, d1 = BIGF, d2m = BIGF, d3 = BIGF;
#pragma unroll 2
        for (int jj = 0; jj < ncand; ++jj) {
            ulonglong2 g = s_cand[jj];             // single LDS.128 broadcast
            float gxs, gxs2; upk2(gxs, gxs2, g.x);
            float dx  = xn + gxs;
            float dxx = dx * dx;
            unsigned long long dxx2 = pk2(dxx, dxx);
            unsigned long long dya = addx2(ny01, g.y);
            unsigned long long d2a = fmax2(dya, dya, dxx2);
            unsigned long long dyb = addx2(ny23, g.y);
            unsigned long long d2b = fmax2(dyb, dyb, dxx2);
            float a, bx, c, dd;
            upk2(a, bx, d2a); upk2(c, dd, d2b);
            d0  = fminf(d0,  a);
            d1  = fminf(d1,  bx);
            d2m = fminf(d2m, c);
            d3  = fminf(d3,  dd);
        }

        // ---- term1 partial: sum p*sqrt(min d2), sum p ----
        float t1 = p0*sqrtf(d0) + p1*sqrtf(d1) + p2*sqrtf(d2m) + p3*sqrtf(d3);
        float ps = p0 + p1 + p2 + p3;
#pragma unroll
        for (int off = 16; off > 0; off >>= 1) {
            t1 += __shfl_down_sync(0xffffffffu, t1, off);
            ps += __shfl_down_sync(0xffffffffu, ps, off);
        }
        __syncthreads();   // protect s_red reuse
        if (lane == 0) { s_red[wid] = t1; s_red[NWARP+wid] = ps; }
        __syncthreads();
        if (tid == 0) {
            float a = 0.f, c2 = 0.f;
#pragma unroll
            for (int w = 0; w < NWARP; ++w) { a += s_red[w]; c2 += s_red[NWARP+w]; }
            g_t1part[tb] = a;
            g_ppart [tb] = c2;
        }
    }

    // ==================== common tail: last-block finalize ====================
    __threadfence();
    __syncthreads();
    if (tid == 0) s_last = (atomicAdd(&g_sem, 1u) == (unsigned)(TOTBLK - 1));
    __syncthreads();
    if (!s_last) return;

    // term2 total: fixed-order deterministic sum of 768 values
    float acc = 0.f;
#pragma unroll
    for (int t = tid; t < BB*MM; t += NT) acc += g_jval[t];
#pragma unroll
    for (int off = 16; off > 0; off >>= 1)
        acc += __shfl_down_sync(0xffffffffu, acc, off);

    // term1 ratios: warps 0..3, one image each (fixed-order)
    if (wid < BB) {
        float nu = 0.f, de = 0.f;
        for (int c = lane; c < NCHUNK; c += 32) {
            nu += g_t1part[wid*NCHUNK + c];
            de += g_ppart [wid*NCHUNK + c];
        }
#pragma unroll
        for (int off = 16; off > 0; off >>= 1) {
            nu += __shfl_down_sync(0xffffffffu, nu, off);
            de += __shfl_down_sync(0xffffffffu, de, off);
        }
        if (lane == 0) s_t1[wid] = nu / (de + EPSF);
    }
    if (lane == 0) s_red[wid] = acc;
    __syncthreads();

    if (tid == 0) {
        float t2 = 0.f;
#pragma unroll
        for (int w = 0; w < NWARP; ++w) t2 += s_red[w];
        float t1sum = 0.f;
#pragma unroll
        for (int bb = 0; bb < BB; ++bb) t1sum += s_t1[bb];
        out[0] = t1sum * (1.0f/(float)BB) + t2 * (1.0f/(float)(BB*MM));
        g_sem = 0u;                                // reset for next replay
    }
}

extern "C" void kernel_launch(void* const* d_in, const int* in_sizes, int n_in,
                              void* d_out, int out_size)
{
    const float* pm  = nullptr;
    const float* gt  = nullptr;
    const float* osz = nullptr;
    for (int i = 0; i < n_in; ++i) {
        if      (in_sizes[i] == BB*NPIX) pm  = (const float*)d_in[i];
        else if (in_sizes[i] == BB*MM*2) gt  = (const float*)d_in[i];
        else if (in_sizes[i] == BB*2)    osz = (const float*)d_in[i];
    }
    whd_all<<<TOTBLK, NT>>>(pm, gt, osz, (float*)d_out);
    (void)out_size;
}

// round 10
// speedup vs baseline: 1.2720x; 1.2720x over previous
#include <cuda_runtime.h>
#include <cstddef>

// ---- problem constants ----
#define HH 384
#define WW 384
#define NPIX (HH*WW)          // 147456
#define BB 4
#define MM 192
#define NT 128
#define TILE_W 32
#define TILE_H 32
#define TILES_X (WW/TILE_W)            // 12
#define TILES_Y (HH/TILE_H)            // 12
#define NCHUNK (TILES_X*TILES_Y)       // 144
#define NBLK1 (BB*NCHUNK)              // 576
#define NBLK2 ((BB*MM)/4)              // 192 (4 warps/block, 1 warp per (b,j))
#define TOTBLK (NBLK1+NBLK2)           // 768 -> all resident (<=8 CTAs/SM, 128 thr)
#define NWARP (NT/32)                  // 4
#define EPSF 1e-6f
#define MAX_DISTF 543.0580079975699f   // sqrt(384^2+384^2)
#define EPS_OVER_MAX 1.8414263e-9f     // 1e-6 / MAX_DIST
#define C2MIN 0.999999f
#define BIGF 3.4e38f

// ---- scratch (static device globals; g_sem reset by finalizer) ----
__device__ float    g_t1part[NBLK1];
__device__ float    g_ppart [NBLK1];
__device__ float    g_jval  [BB*MM];
__device__ unsigned g_sem;

// ---- packed f32x2 helpers ----
__device__ __forceinline__ unsigned long long pk2(float a, float b) {
    unsigned long long r;
    asm("mov.b64 %0, {%1, %2};" : "=l"(r) : "f"(a), "f"(b));
    return r;
}
__device__ __forceinline__ void upk2(float& a, float& b, unsigned long long v) {
    asm("mov.b64 {%0, %1}, %2;" : "=f"(a), "=f"(b) : "l"(v));
}
__device__ __forceinline__ unsigned long long addx2(unsigned long long a, unsigned long long b) {
    unsigned long long r;
    asm("add.rn.f32x2 %0, %1, %2;" : "=l"(r) : "l"(a), "l"(b));
    return r;
}
__device__ __forceinline__ unsigned long long fmax2(unsigned long long a, unsigned long long b,
                                                    unsigned long long c) {
    unsigned long long r;
    asm("fma.rn.f32x2 %0, %1, %2, %3;" : "=l"(r) : "l"(a), "l"(b), "l"(c));
    return r;
}

__global__ __launch_bounds__(NT, 8)
void whd_all(const float* __restrict__ pm,
             const float* __restrict__ gt,
             const float* __restrict__ osz,
             float* __restrict__ out)
{
    __shared__ ulonglong2 s_cand[MM];   // {(-gx,-gx), (-gy,-gy)} packed -> LDS.128
    __shared__ float s_red[NWARP*2];
    __shared__ float s_t1[BB];
    __shared__ int   s_n;
    __shared__ bool  s_last;

    const int tid  = threadIdx.x;
    const int lane = tid & 31;
    const int wid  = tid >> 5;
    const int bid  = blockIdx.x;

    if (tid == 0) s_n = 0;

    if (bid < NBLK2) {
        // ==================== term2 role: one warp per (b,j) ====================
        // Exact windowed min of d2*c^2; lane<->column coalesced scan, no int div,
        // dx^2 hoisted; certified exact via edge-gap bound.
        const int wg = bid * NWARP + wid;          // 0..767
        const int b  = wg / MM;
        const int j  = wg - b * MM;

        const float fy = osz[2*b+0] * (1.0f/(float)HH);
        const float fx = osz[2*b+1] * (1.0f/(float)WW);
        const float grow = gt[((size_t)b*MM + j)*2 + 0];
        const float gcol = gt[((size_t)b*MM + j)*2 + 1];
        const float* pmb = pm + (size_t)b * NPIX;

        const int cx = (int)gcol;
        const int cy = (int)grow;

        float U;
        int r = 15;                                 // 31x31 start: nearly always certifies
        for (;;) {
            int x0 = cx - r, x1 = cx + r, y0 = cy - r, y1 = cy + r;
            const bool clx0 = (x0 <= 0), clx1 = (x1 >= WW-1);
            const bool cly0 = (y0 <= 0), cly1 = (y1 >= HH-1);
            x0 = max(x0, 0); y0 = max(y0, 0);
            x1 = min(x1, WW-1); y1 = min(y1, HH-1);

            float kmin = BIGF;
            for (int xs = x0; xs <= x1; xs += 32) {  // column strips of 32 lanes
                int px = xs + lane;
                if (px <= x1) {
                    float dxv = ((float)px - gcol) * fx;
                    float dx2 = dxv * dxv;
                    const float* rowp = pmb + (size_t)y0 * WW + px;
                    float dyv = ((float)y0 - grow) * fy;
#pragma unroll 4
                    for (int y = y0; y <= y1; ++y) {
                        float p  = *rowp;            // coalesced across lanes
                        rowp += WW;
                        float d2 = fmaf(dyv, dyv, dx2);
                        dyv += fy;
                        float pp = p*p;
                        float c  = __fdividef(1.0f, pp*pp + EPS_OVER_MAX);
                        kmin = fminf(kmin, d2 * (c*c));
                    }
                }
            }
            unsigned u = __reduce_min_sync(0xffffffffu, __float_as_uint(kmin));
            U = __uint_as_float(u);

            if (clx0 && clx1 && cly0 && cly1) break;   // full image: exact

            const float GBIG = 1.0e18f;
            float gxl = clx0 ? GBIG : (gcol - (float)x0 + 1.0f) * fx;
            float gxh = clx1 ? GBIG : ((float)x1 + 1.0f - gcol) * fx;
            float gyl = cly0 ? GBIG : (grow - (float)y0 + 1.0f) * fy;
            float gyh = cly1 ? GBIG : ((float)y1 + 1.0f - grow) * fy;
            float G = fminf(fminf(gxl, gxh), fminf(gyl, gyh));
            if (U <= G*G*C2MIN) break;                 // exactness certified
            r <<= 1;                                   // rare
        }
        if (lane == 0)
            g_jval[wg] = fminf(sqrtf(U), MAX_DISTF);
    } else {
        // ==================== term1 role: one 32x32 pixel tile ====================
        const int tb    = bid - NBLK2;             // 0..575
        const int b     = tb / NCHUNK;
        const int chunk = tb - b * NCHUNK;
        const int tile_x = chunk % TILES_X;
        const int tile_y = chunk / TILES_X;

        const float* pmb = pm + (size_t)b * NPIX;
        const float* gtb = gt + (size_t)b * MM * 2;

        const int col0 = tile_x * TILE_W;
        const int row0 = tile_y * TILE_H;
        const int colg = col0 + lane;              // lane <-> column
        const int rowt = row0 + wid * 8;           // this thread: rows rowt..rowt+7

        // ---- issue ALL independent loads first (no osz dependency) ----
        float pv[8];
#pragma unroll
        for (int k = 0; k < 8; ++k)
            pv[k] = pmb[(size_t)(rowt + k)*WW + colg];          // coalesced

        // raw GT coords (two per thread); addresses index-only
        float gry0 = gtb[2*tid + 0];
        float grx0 = gtb[2*tid + 1];
        float gry1 = 0.f, grx1 = 0.f;
        if (tid < MM - NT) {                        // tid < 64: second point
            gry1 = gtb[2*(tid + NT) + 0];
            grx1 = gtb[2*(tid + NT) + 1];
        }
        const float fy = osz[2*b+0] * (1.0f/(float)HH);
        const float fx = osz[2*b+1] * (1.0f/(float)WW);

        const float xn = (float)colg * fx;          // shared across 8 px of this thread
        unsigned long long nyp[4];
#pragma unroll
        for (int k = 0; k < 4; ++k)
            nyp[k] = pk2((float)(rowt + 2*k) * fy, (float)(rowt + 2*k + 1) * fy);

        // ---- phase 0: exact candidate culling (triangle inequality) ----
        const float cxn = ((float)col0 + 15.5f) * fx;
        const float cyn = ((float)row0 + 15.5f) * fy;
        const float hx = 15.5f * fx, hy = 15.5f * fy;
        const float Dh = sqrtf(hx*hx + hy*hy);      // tile half-diagonal (normalized)

        float gxn0 = grx0 * fx, gyn0 = gry0 * fy;
        float ax0 = gxn0 - cxn, ay0 = gyn0 - cyn;
        float dc0 = sqrtf(fmaf(ax0, ax0, ay0*ay0));
        float dc1 = BIGF, gxn1 = 0.f, gyn1 = 0.f;
        if (tid < MM - NT) {
            gxn1 = grx1 * fx; gyn1 = gry1 * fy;
            float ax1 = gxn1 - cxn, ay1 = gyn1 - cyn;
            dc1 = sqrtf(fmaf(ax1, ax1, ay1*ay1));
        }
        float dcm = fminf(dc0, dc1);
        unsigned wm = __reduce_min_sync(0xffffffffu, __float_as_uint(dcm));
        if (lane == 0) s_red[wid] = __uint_as_float(wm);
        __syncthreads();
        float Uc = fminf(fminf(s_red[0], s_red[1]), fminf(s_red[2], s_red[3]));
        // point can be a tile pixel's argmin only if dc <= Uc + 2*Dh (+ slack)
        float thr = Uc + 2.0f*Dh + 1e-2f;
        if (dc0 <= thr) {
            int slot = atomicAdd(&s_n, 1);
            ulonglong2 v; v.x = pk2(-gxn0, -gxn0); v.y = pk2(-gyn0, -gyn0);
            s_cand[slot] = v;
        }
        if (dc1 <= thr) {
            int slot = atomicAdd(&s_n, 1);
            ulonglong2 v; v.x = pk2(-gxn1, -gxn1); v.y = pk2(-gyn1, -gyn1);
            s_cand[slot] = v;
        }
        __syncthreads();
        const int ncand = s_n;

        // ---- hot loop over candidates only ----
        unsigned long long dmn[4] = {pk2(BIGF,BIGF), pk2(BIGF,BIGF),
                                     pk2(BIGF,BIGF), pk2(BIGF,BIGF)};
#pragma unroll 2
        for (int jj = 0; jj < ncand; ++jj) {
            ulonglong2 g = s_cand[jj];              // single LDS.128 broadcast
            float gxs, gxsdup; upk2(gxs, gxsdup, g.x);
            float dx  = xn + gxs;
            float dxx = dx * dx;
            unsigned long long dxx2 = pk2(dxx, dxx);
#pragma unroll
            for (int k = 0; k < 4; ++k) {
                unsigned long long dya = addx2(nyp[k], g.y);
                unsigned long long d2a = fmax2(dya, dya, dxx2);
                float a, bx, c0, c1;
                upk2(a, bx, d2a);
                upk2(c0, c1, dmn[k]);
                dmn[k] = pk2(fminf(c0, a), fminf(c1, bx));
            }
        }

        // ---- term1 partial: sum p*sqrt(min d2), sum p ----
        float t1 = 0.f, ps = 0.f;
#pragma unroll
        for (int k = 0; k < 4; ++k) {
            float a, bx; upk2(a, bx, dmn[k]);       // rows rowt+2k, rowt+2k+1
            t1 += pv[2*k]   * sqrtf(a);
            t1 += pv[2*k+1] * sqrtf(bx);
            ps += pv[2*k] + pv[2*k+1];
        }
#pragma unroll
        for (int off = 16; off > 0; off >>= 1) {
            t1 += __shfl_down_sync(0xffffffffu, t1, off);
            ps += __shfl_down_sync(0xffffffffu, ps, off);
        }
        __syncthreads();   // protect s_red reuse
        if (lane == 0) { s_red[wid] = t1; s_red[NWARP+wid] = ps; }
        __syncthreads();
        if (tid == 0) {
            float a = 0.f, c2 = 0.f;
#pragma unroll
            for (int w = 0; w < NWARP; ++w) { a += s_red[w]; c2 += s_red[NWARP+w]; }
            g_t1part[tb] = a;
            g_ppart [tb] = c2;
        }
    }

    // ==================== common tail: last-block finalize ====================
    __threadfence();
    __syncthreads();
    if (tid == 0) s_last = (atomicAdd(&g_sem, 1u) == (unsigned)(TOTBLK - 1));
    __syncthreads();
    if (!s_last) return;

    // term2 total: fixed-order deterministic sum of 768 values
    float acc = 0.f;
#pragma unroll
    for (int t = tid; t < BB*MM; t += NT) acc += g_jval[t];
#pragma unroll
    for (int off = 16; off > 0; off >>= 1)
        acc += __shfl_down_sync(0xffffffffu, acc, off);

    // term1 ratios: warps 0..3, one image each (fixed-order)
    {
        float nu = 0.f, de = 0.f;
        for (int c = lane; c < NCHUNK; c += 32) {
            nu += g_t1part[wid*NCHUNK + c];
            de += g_ppart [wid*NCHUNK + c];
        }
#pragma unroll
        for (int off = 16; off > 0; off >>= 1) {
            nu += __shfl_down_sync(0xffffffffu, nu, off);
            de += __shfl_down_sync(0xffffffffu, de, off);
        }
        if (lane == 0) s_t1[wid] = nu / (de + EPSF);
    }
    if (lane == 0) s_red[wid] = acc;
    __syncthreads();

    if (tid == 0) {
        float t2 = 0.f;
#pragma unroll
        for (int w = 0; w < NWARP; ++w) t2 += s_red[w];
        float t1sum = 0.f;
#pragma unroll
        for (int bb = 0; bb < BB; ++bb) t1sum += s_t1[bb];
        out[0] = t1sum * (1.0f/(float)BB) + t2 * (1.0f/(float)(BB*MM));
        g_sem = 0u;                                // reset for next replay
    }
}

extern "C" void kernel_launch(void* const* d_in, const int* in_sizes, int n_in,
                              void* d_out, int out_size)
{
    const float* pm  = nullptr;
    const float* gt  = nullptr;
    const float* osz = nullptr;
    for (int i = 0; i < n_in; ++i) {
        if      (in_sizes[i] == BB*NPIX) pm  = (const float*)d_in[i];
        else if (in_sizes[i] == BB*MM*2) gt  = (const float*)d_in[i];
        else if (in_sizes[i] == BB*2)    osz = (const float*)d_in[i];
    }
    whd_all<<<TOTBLK, NT>>>(pm, gt, osz, (float*)d_out);
    (void)out_size;
}

// round 11
// speedup vs baseline: 1.2829x; 1.0086x over previous
#include <cuda_runtime.h>
#include <cstddef>

// ---- problem constants ----
#define HH 384
#define WW 384
#define NPIX (HH*WW)          // 147456
#define BB 4
#define MM 192
#define NT 128
#define TILE_W 32
#define TILE_H 32
#define TILES_X (WW/TILE_W)            // 12
#define TILES_Y (HH/TILE_H)            // 12
#define NCHUNK (TILES_X*TILES_Y)       // 144
#define NBLK1 (BB*NCHUNK)              // 576
#define NBLK2 ((BB*MM)/4)              // 192 (4 warps/block, 1 warp per (b,j))
#define TOTBLK (NBLK1+NBLK2)           // 768 -> all resident (128 thr, <=8 CTAs/SM)
#define NWARP (NT/32)                  // 4
#define EPSF 1e-6f
#define MAX_DISTF 543.0580079975699f   // sqrt(384^2+384^2)
#define EPS_OVER_MAX 1.8414263e-9f     // 1e-6 / MAX_DIST
#define CMINR 0.999999f                // lower bound on c (c = 1/(p^4+eps') >= ~1-2e-9)
#define BIGF 3.4e38f

// ---- scratch (static device globals; g_sem reset by finalizer) ----
__device__ float    g_t1part[NBLK1];
__device__ float    g_ppart [NBLK1];
__device__ float    g_jval  [BB*MM];
__device__ unsigned g_sem;

// ---- packed f32x2 helpers ----
__device__ __forceinline__ unsigned long long pk2(float a, float b) {
    unsigned long long r;
    asm("mov.b64 %0, {%1, %2};" : "=l"(r) : "f"(a), "f"(b));
    return r;
}
__device__ __forceinline__ void upk2(float& a, float& b, unsigned long long v) {
    asm("mov.b64 {%0, %1}, %2;" : "=f"(a), "=f"(b) : "l"(v));
}
__device__ __forceinline__ unsigned long long addx2(unsigned long long a, unsigned long long b) {
    unsigned long long r;
    asm("add.rn.f32x2 %0, %1, %2;" : "=l"(r) : "l"(a), "l"(b));
    return r;
}
__device__ __forceinline__ unsigned long long fmax2(unsigned long long a, unsigned long long b,
                                                    unsigned long long c) {
    unsigned long long r;
    asm("fma.rn.f32x2 %0, %1, %2, %3;" : "=l"(r) : "l"(a), "l"(b), "l"(c));
    return r;
}

__global__ __launch_bounds__(NT, 8)
void whd_all(const float* __restrict__ pm,
             const float* __restrict__ gt,
             const float* __restrict__ osz,
             float* __restrict__ out)
{
    __shared__ ulonglong2 s_cand[MM];   // {(-gx,-gx), (-gy,-gy)} packed -> LDS.128
    __shared__ float s_red[NWARP*2];
    __shared__ float s_t1[BB];
    __shared__ int   s_n;
    __shared__ bool  s_last;

    const int tid  = threadIdx.x;
    const int lane = tid & 31;
    const int wid  = tid >> 5;
    const int bid  = blockIdx.x;

    if (tid == 0) s_n = 0;

    if (bid < NBLK2) {
        // ==================== term2 role: one warp per (b,j) ====================
        // Maximize m = q * rsqrt(d2), q = p^4 + eps'  (equiv. to minimizing d/q).
        // Lane<->column coalesced scan, no divides. Certified exact when
        // m_max * G * CMINR >= 1 (any outside pixel has value d*c >= G*CMINR).
        const int wg = bid * NWARP + wid;          // 0..767
        const int b  = wg / MM;
        const int j  = wg - b * MM;

        const float fy = osz[2*b+0] * (1.0f/(float)HH);
        const float fx = osz[2*b+1] * (1.0f/(float)WW);
        const float grow = gt[((size_t)b*MM + j)*2 + 0];
        const float gcol = gt[((size_t)b*MM + j)*2 + 1];
        const float* pmb = pm + (size_t)b * NPIX;

        const int cx = (int)gcol;
        const int cy = (int)grow;

        float M;                                    // warp max of m
        int r = 12;                                 // 25x25 start: certifies ~always
        for (;;) {
            int x0 = cx - r, x1 = cx + r, y0 = cy - r, y1 = cy + r;
            const bool clx0 = (x0 <= 0), clx1 = (x1 >= WW-1);
            const bool cly0 = (y0 <= 0), cly1 = (y1 >= HH-1);
            x0 = max(x0, 0); y0 = max(y0, 0);
            x1 = min(x1, WW-1); y1 = min(y1, HH-1);

            float mmax = 0.f;
            for (int xs = x0; xs <= x1; xs += 32) {  // column strips of 32 lanes
                int px = xs + lane;
                if (px <= x1) {
                    float dxv = ((float)px - gcol) * fx;
                    float dx2 = dxv * dxv;
                    const float* rowp = pmb + (size_t)y0 * WW + px;
                    float dyv = ((float)y0 - grow) * fy;
#pragma unroll 4
                    for (int y = y0; y <= y1; ++y) {
                        float p  = *rowp;            // coalesced across lanes
                        rowp += WW;
                        float d2 = fmaf(dyv, dyv, dx2);
                        dyv += fy;
                        float pp = p*p;
                        float q  = fmaf(pp, pp, EPS_OVER_MAX);   // p^4 + eps'
                        float m  = q * rsqrtf(d2);               // d2=0 -> inf (ok)
                        mmax = fmaxf(mmax, m);
                    }
                }
            }
            unsigned u = __reduce_max_sync(0xffffffffu, __float_as_uint(mmax));
            M = __uint_as_float(u);

            if (clx0 && clx1 && cly0 && cly1) break;   // full image: exact

            const float GBIG = 1.0e18f;
            float gxl = clx0 ? GBIG : (gcol - (float)x0 + 1.0f) * fx;
            float gxh = clx1 ? GBIG : ((float)x1 + 1.0f - gcol) * fx;
            float gyl = cly0 ? GBIG : (grow - (float)y0 + 1.0f) * fy;
            float gyh = cly1 ? GBIG : ((float)y1 + 1.0f - grow) * fy;
            float G = fminf(fminf(gxl, gxh), fminf(gyl, gyh));
            if (M * G * CMINR >= 1.0f) break;          // exactness certified
            r <<= 1;                                   // rare
        }
        if (lane == 0)
            g_jval[wg] = fminf(__fdividef(1.0f, M), MAX_DISTF);  // min d*c, clipped
    } else {
        // ==================== term1 role: one 32x32 pixel tile ====================
        // Thread <-> 8-column run of one row: 2x LDG.128 (MLP_p1=2, low L1tex queue).
        const int tb    = bid - NBLK2;             // 0..575
        const int b     = tb / NCHUNK;
        const int chunk = tb - b * NCHUNK;
        const int tile_x = chunk % TILES_X;
        const int tile_y = chunk / TILES_X;

        const float* pmb = pm + (size_t)b * NPIX;
        const float* gtb = gt + (size_t)b * MM * 2;

        const int col0 = tile_x * TILE_W;
        const int row0 = tile_y * TILE_H;
        const int rowg = row0 + (tid >> 2);        // this thread's row (32 rows x 4 thr)
        const int colt = col0 + (tid & 3) * 8;     // 8 consecutive columns

        // ---- issue ALL independent loads first ----
        const float4 pva = *reinterpret_cast<const float4*>(pmb + (size_t)rowg*WW + colt);
        const float4 pvb = *reinterpret_cast<const float4*>(pmb + (size_t)rowg*WW + colt + 4);

        // raw GT coords (two per thread); addresses index-only
        float gry0 = gtb[2*tid + 0];
        float grx0 = gtb[2*tid + 1];
        float gry1 = 0.f, grx1 = 0.f;
        if (tid < MM - NT) {                        // tid < 64: second point
            gry1 = gtb[2*(tid + NT) + 0];
            grx1 = gtb[2*(tid + NT) + 1];
        }
        const float fy = osz[2*b+0] * (1.0f/(float)HH);
        const float fx = osz[2*b+1] * (1.0f/(float)WW);

        const float yn = (float)rowg * fy;          // shared across 8 px of this thread
        unsigned long long nxp[4];
#pragma unroll
        for (int k = 0; k < 4; ++k)
            nxp[k] = pk2((float)(colt + 2*k) * fx, (float)(colt + 2*k + 1) * fx);

        // ---- phase 0: exact candidate culling (triangle inequality) ----
        const float cxn = ((float)col0 + 15.5f) * fx;
        const float cyn = ((float)row0 + 15.5f) * fy;
        const float hx = 15.5f * fx, hy = 15.5f * fy;
        const float Dh = sqrtf(hx*hx + hy*hy);      // tile half-diagonal (normalized)

        float gxn0 = grx0 * fx, gyn0 = gry0 * fy;
        float ax0 = gxn0 - cxn, ay0 = gyn0 - cyn;
        float dc0 = sqrtf(fmaf(ax0, ax0, ay0*ay0));
        float dc1 = BIGF, gxn1 = 0.f, gyn1 = 0.f;
        if (tid < MM - NT) {
            gxn1 = grx1 * fx; gyn1 = gry1 * fy;
            float ax1 = gxn1 - cxn, ay1 = gyn1 - cyn;
            dc1 = sqrtf(fmaf(ax1, ax1, ay1*ay1));
        }
        float dcm = fminf(dc0, dc1);
        unsigned wm = __reduce_min_sync(0xffffffffu, __float_as_uint(dcm));
        if (lane == 0) s_red[wid] = __uint_as_float(wm);
        __syncthreads();
        float Uc = fminf(fminf(s_red[0], s_red[1]), fminf(s_red[2], s_red[3]));
        // point can be a tile pixel's argmin only if dc <= Uc + 2*Dh (+ slack)
        float thr = Uc + 2.0f*Dh + 1e-2f;
        if (dc0 <= thr) {
            int slot = atomicAdd(&s_n, 1);
            ulonglong2 v; v.x = pk2(-gxn0, -gxn0); v.y = pk2(-gyn0, -gyn0);
            s_cand[slot] = v;
        }
        if (dc1 <= thr) {
            int slot = atomicAdd(&s_n, 1);
            ulonglong2 v; v.x = pk2(-gxn1, -gxn1); v.y = pk2(-gyn1, -gyn1);
            s_cand[slot] = v;
        }
        __syncthreads();
        const int ncand = s_n;

        // ---- hot loop over candidates only ----
        unsigned long long dmn[4] = {pk2(BIGF,BIGF), pk2(BIGF,BIGF),
                                     pk2(BIGF,BIGF), pk2(BIGF,BIGF)};
#pragma unroll 2
        for (int jj = 0; jj < ncand; ++jj) {
            ulonglong2 g = s_cand[jj];              // single LDS.128 broadcast
            float gys, gysdup; upk2(gys, gysdup, g.y);
            float dy  = yn + gys;                   // shared across 8 columns
            float dyy = dy * dy;
            unsigned long long dyy2 = pk2(dyy, dyy);
#pragma unroll
            for (int k = 0; k < 4; ++k) {
                unsigned long long dxp = addx2(nxp[k], g.x);
                unsigned long long d2a = fmax2(dxp, dxp, dyy2);
                float a, bx, c0, c1;
                upk2(a, bx, d2a);
                upk2(c0, c1, dmn[k]);
                dmn[k] = pk2(fminf(c0, a), fminf(c1, bx));
            }
        }

        // ---- term1 partial: sum p*sqrt(min d2), sum p ----
        float d2m[8];
#pragma unroll
        for (int k = 0; k < 4; ++k) upk2(d2m[2*k], d2m[2*k+1], dmn[k]);
        float t1 = pva.x*sqrtf(d2m[0]) + pva.y*sqrtf(d2m[1])
                 + pva.z*sqrtf(d2m[2]) + pva.w*sqrtf(d2m[3])
                 + pvb.x*sqrtf(d2m[4]) + pvb.y*sqrtf(d2m[5])
                 + pvb.z*sqrtf(d2m[6]) + pvb.w*sqrtf(d2m[7]);
        float ps = (pva.x + pva.y + pva.z + pva.w)
                 + (pvb.x + pvb.y + pvb.z + pvb.w);
#pragma unroll
        for (int off = 16; off > 0; off >>= 1) {
            t1 += __shfl_down_sync(0xffffffffu, t1, off);
            ps += __shfl_down_sync(0xffffffffu, ps, off);
        }
        __syncthreads();   // protect s_red reuse
        if (lane == 0) { s_red[wid] = t1; s_red[NWARP+wid] = ps; }
        __syncthreads();
        if (tid == 0) {
            float a = 0.f, c2 = 0.f;
#pragma unroll
            for (int w = 0; w < NWARP; ++w) { a += s_red[w]; c2 += s_red[NWARP+w]; }
            g_t1part[tb] = a;
            g_ppart [tb] = c2;
        }
    }

    // ==================== common tail: last-block finalize ====================
    __threadfence();
    __syncthreads();
    if (tid == 0) s_last = (atomicAdd(&g_sem, 1u) == (unsigned)(TOTBLK - 1));
    __syncthreads();
    if (!s_last) return;

    // term2 total: fixed-order deterministic sum of 768 values
    float acc = 0.f;
#pragma unroll
    for (int t = tid; t < BB*MM; t += NT) acc += g_jval[t];
#pragma unroll
    for (int off = 16; off > 0; off >>= 1)
        acc += __shfl_down_sync(0xffffffffu, acc, off);

    // term1 ratios: warps 0..3, one image each (fixed-order)
    {
        float nu = 0.f, de = 0.f;
        for (int c = lane; c < NCHUNK; c += 32) {
            nu += g_t1part[wid*NCHUNK + c];
            de += g_ppart [wid*NCHUNK + c];
        }
#pragma unroll
        for (int off = 16; off > 0; off >>= 1) {
            nu += __shfl_down_sync(0xffffffffu, nu, off);
            de += __shfl_down_sync(0xffffffffu, de, off);
        }
        if (lane == 0) s_t1[wid] = nu / (de + EPSF);
    }
    if (lane == 0) s_red[wid] = acc;
    __syncthreads();

    if (tid == 0) {
        float t2 = 0.f;
#pragma unroll
        for (int w = 0; w < NWARP; ++w) t2 += s_red[w];
        float t1sum = 0.f;
#pragma unroll
        for (int bb = 0; bb < BB; ++bb) t1sum += s_t1[bb];
        out[0] = t1sum * (1.0f/(float)BB) + t2 * (1.0f/(float)(BB*MM));
        g_sem = 0u;                                // reset for next replay
    }
}

extern "C" void kernel_launch(void* const* d_in, const int* in_sizes, int n_in,
                              void* d_out, int out_size)
{
    const float* pm  = nullptr;
    const float* gt  = nullptr;
    const float* osz = nullptr;
    for (int i = 0; i < n_in; ++i) {
        if      (in_sizes[i] == BB*NPIX) pm  = (const float*)d_in[i];
        else if (in_sizes[i] == BB*MM*2) gt  = (const float*)d_in[i];
        else if (in_sizes[i] == BB*2)    osz = (const float*)d_in[i];
    }
    whd_all<<<TOTBLK, NT>>>(pm, gt, osz, (float*)d_out);
    (void)out_size;
}